// round 1
// baseline (speedup 1.0000x reference)
#include <cuda_runtime.h>

#define DD   128
#define BD   16384      // DD*DD
#define SROW 132        // padded smem row stride (floats), multiple of 4 for float4

__global__ __launch_bounds__(256, 1)
void magnus_kernel(const float* __restrict__ t0,
                   const float* __restrict__ hptr,
                   const float* __restrict__ y0,
                   const float* __restrict__ A0,
                   const float* __restrict__ W,
                   float* __restrict__ out, int B)
{
    extern __shared__ float sm[];
    float* As  = sm;                    // 128 x SROW
    float* Ws  = sm + DD * SROW;        // 128 x SROW
    float* vec = sm + 2 * DD * SROW;    // v[128], vn[128], yv[128]

    const int b   = blockIdx.x;
    const int tid = threadIdx.x;

    const float h    = hptr[0];
    const float t0b  = t0[b];
    const float SQ3_6 = 0.28867513459481287f;   // sqrt(3)/6
    const float t1 = t0b + (0.5f - SQ3_6) * h;
    const float t2 = t0b + (0.5f + SQ3_6) * h;
    const float tm = t0b + 0.5f * h;
    const float c12 = h * h * h * (1.0f / 12.0f);

    const float4* A0g = (const float4*)(A0 + (size_t)b * BD);
    const float4* Wg  = (const float4*)(W  + (size_t)b * BD);
    float4* o1 = (float4*)(out + (size_t)B * DD + (size_t)b * BD);
    float4* o2 = (float4*)(out + (size_t)B * DD + (size_t)B * BD + (size_t)b * BD);

    // ---- Phase 1: stream A0, W -> smem; emit A1, A2 outputs on the way ----
    #pragma unroll
    for (int it = 0; it < BD / 4 / 256; ++it) {
        int i = tid + it * 256;
        float4 a = A0g[i];
        float4 w = Wg[i];
        float4 x1, x2;
        x1.x = fmaf(t1, w.x, a.x); x1.y = fmaf(t1, w.y, a.y);
        x1.z = fmaf(t1, w.z, a.z); x1.w = fmaf(t1, w.w, a.w);
        x2.x = fmaf(t2, w.x, a.x); x2.y = fmaf(t2, w.y, a.y);
        x2.z = fmaf(t2, w.z, a.z); x2.w = fmaf(t2, w.w, a.w);
        o1[i] = x1;
        o2[i] = x2;
        int row = i >> 5;            // (i*4)/128
        int col = (i & 31) << 2;
        *(float4*)(As + row * SROW + col) = a;
        *(float4*)(Ws + row * SROW + col) = w;
    }
    __syncthreads();

    // ---- Phase 2: commutator  acc = A0 @ W - W @ A0  (8x8 register tile) ----
    const int ty = tid >> 4, tx = tid & 15;
    const int i0 = ty << 3, j0 = tx << 3;

    float acc[8][8];
    #pragma unroll
    for (int r = 0; r < 8; ++r)
        #pragma unroll
        for (int c = 0; c < 8; ++c) acc[r][c] = 0.0f;

    for (int k = 0; k < DD; ++k) {
        float ai[8], win[8], aj[8], wj[8];
        #pragma unroll
        for (int r = 0; r < 8; ++r) {
            ai[r]  =  As[(i0 + r) * SROW + k];
            win[r] = -Ws[(i0 + r) * SROW + k];
        }
        float4 q;
        q = *(const float4*)(Ws + k * SROW + j0);     wj[0]=q.x; wj[1]=q.y; wj[2]=q.z; wj[3]=q.w;
        q = *(const float4*)(Ws + k * SROW + j0 + 4); wj[4]=q.x; wj[5]=q.y; wj[6]=q.z; wj[7]=q.w;
        q = *(const float4*)(As + k * SROW + j0);     aj[0]=q.x; aj[1]=q.y; aj[2]=q.z; aj[3]=q.w;
        q = *(const float4*)(As + k * SROW + j0 + 4); aj[4]=q.x; aj[5]=q.y; aj[6]=q.z; aj[7]=q.w;
        #pragma unroll
        for (int r = 0; r < 8; ++r)
            #pragma unroll
            for (int c = 0; c < 8; ++c) {
                acc[r][c] = fmaf(ai[r],  wj[c], acc[r][c]);
                acc[r][c] = fmaf(win[r], aj[c], acc[r][c]);
            }
    }
    __syncthreads();   // all matmul reads of As/Ws complete

    // ---- Phase 3: Omega = h*(A0 + tm*W) - (h^3/12)*comm, in-place into As ----
    // Each thread exclusively owns its 8x8 tile (read own + overwrite own).
    #pragma unroll
    for (int r = 0; r < 8; ++r)
        #pragma unroll
        for (int c = 0; c < 8; ++c) {
            int i = i0 + r, j = j0 + c;
            float m = fmaf(tm, Ws[i * SROW + j], As[i * SROW + j]);
            As[i * SROW + j] = fmaf(h, m, -c12 * acc[r][c]);
        }
    __syncthreads();

    // ---- Phase 4: y = expm(Omega) @ y0 via Taylor mat-vecs (14 terms) ----
    float* v  = vec;
    float* vn = vec + DD;
    float* yv = vec + 2 * DD;
    if (tid < DD) {
        float y0i = y0[(size_t)b * DD + tid];
        v[tid]  = y0i;
        yv[tid] = y0i;
    }
    __syncthreads();

    for (int k = 1; k <= 14; ++k) {
        if (tid < DD) {
            const float* Om = As + tid * SROW;
            float s = 0.0f;
            #pragma unroll 8
            for (int j = 0; j < DD; ++j) s = fmaf(Om[j], v[j], s);
            vn[tid] = s * (1.0f / (float)k);
        }
        __syncthreads();
        if (tid < DD) {
            float nv = vn[tid];
            v[tid]   = nv;
            yv[tid] += nv;
        }
        __syncthreads();
    }

    if (tid < DD) out[(size_t)b * DD + tid] = yv[tid];
}

extern "C" void kernel_launch(void* const* d_in, const int* in_sizes, int n_in,
                              void* d_out, int out_size) {
    const float* t0 = (const float*)d_in[0];
    const float* h  = (const float*)d_in[1];
    const float* y0 = (const float*)d_in[2];
    const float* A0 = (const float*)d_in[3];
    const float* W  = (const float*)d_in[4];
    const int B = in_sizes[0];

    size_t smem = (size_t)(2 * DD * SROW + 3 * DD) * sizeof(float);  // ~136.7 KB
    cudaFuncSetAttribute(magnus_kernel, cudaFuncAttributeMaxDynamicSharedMemorySize, (int)smem);
    magnus_kernel<<<B, 256, smem>>>(t0, h, y0, A0, W, (float*)d_out, B);
}

// round 3
// speedup vs baseline: 3.7719x; 3.7719x over previous
#include <cuda_runtime.h>
#include <cuda_bf16.h>
#include <cstdint>

#define DD    128
#define BD    16384          // DD*DD
#define SQ36  0.28867513459481287f   // sqrt(3)/6

// ---- dynamic smem byte offsets ----
#define AOP    0          // bf16 A0 [128x128], row pitch 256B, XOR-swizzled (32KB)
#define WOP    32768      // bf16 W  same layout
#define OMEGA  65536      // fp32 128 x 132 (67584B)
#define VOFF   133120     // v[128]
#define YVOFF  133632     // yv[128]
#define PSOFF  134144     // ps[256]
#define SMEM_REQ 135168

// ---------------- PTX helpers (all sm_80-era, no arch-'a' features) ----------
__device__ __forceinline__ uint32_t smem_u32(const void* p) {
    uint32_t a;
    asm("{ .reg .u64 t; cvta.to.shared.u64 t, %1; cvt.u32.u64 %0, t; }" : "=r"(a) : "l"(p));
    return a;
}
__device__ __forceinline__ void ldsm_x4(uint32_t* r, uint32_t addr) {
    asm volatile("ldmatrix.sync.aligned.m8n8.x4.shared.b16 {%0,%1,%2,%3}, [%4];"
                 : "=r"(r[0]), "=r"(r[1]), "=r"(r[2]), "=r"(r[3]) : "r"(addr));
}
__device__ __forceinline__ void ldsm_x4t(uint32_t* r, uint32_t addr) {
    asm volatile("ldmatrix.sync.aligned.m8n8.x4.trans.shared.b16 {%0,%1,%2,%3}, [%4];"
                 : "=r"(r[0]), "=r"(r[1]), "=r"(r[2]), "=r"(r[3]) : "r"(addr));
}
__device__ __forceinline__ void mma16816(float* d, const uint32_t* a, const uint32_t* b) {
    asm volatile("mma.sync.aligned.m16n8k16.row.col.f32.bf16.bf16.f32 "
                 "{%0,%1,%2,%3}, {%4,%5,%6,%7}, {%8,%9}, {%0,%1,%2,%3};"
                 : "+f"(d[0]), "+f"(d[1]), "+f"(d[2]), "+f"(d[3])
                 : "r"(a[0]), "r"(a[1]), "r"(a[2]), "r"(a[3]), "r"(b[0]), "r"(b[1]));
}
// swizzled address inside a 128x128 bf16 tile (row pitch 256B, 16B chunks XORed per 8 rows)
__device__ __forceinline__ uint32_t taddr(uint32_t base, int row, int col) {
    int chunk = (col >> 3) ^ (row & 7);
    return base + row * 256 + (chunk << 4);
}
__device__ __forceinline__ uint32_t b2u(__nv_bfloat162 v) { return *reinterpret_cast<uint32_t*>(&v); }

__global__ __launch_bounds__(256, 1)
void magnus_kernel(const float* __restrict__ t0, const float* __restrict__ hp,
                   const float* __restrict__ y0,
                   const float* __restrict__ A0, const float* __restrict__ W,
                   float* __restrict__ out, int B)
{
    extern __shared__ char sm[];
    const uint32_t sb = smem_u32(sm);

    const int b    = blockIdx.x;
    const int tid  = threadIdx.x;
    const int lane = tid & 31;
    const int wid  = tid >> 5;

    const float h   = hp[0];
    const float t0b = t0[b];
    const float t1  = t0b + (0.5f - SQ36) * h;
    const float t2  = t0b + (0.5f + SQ36) * h;
    const float tm  = t0b + 0.5f * h;
    const float c12 = h * h * h * (1.0f / 12.0f);

    float* Om = (float*)(sm + OMEGA);   // 128 x 132 fp32
    float* v  = (float*)(sm + VOFF);
    float* yv = (float*)(sm + YVOFF);
    float* ps = (float*)(sm + PSOFF);

    // ---- Phase 1: stream A0,W -> bf16 smem tiles + hM -> Omega; emit A1,A2 ----
    const float4* A0g = (const float4*)(A0 + (size_t)b * BD);
    const float4* Wg  = (const float4*)(W  + (size_t)b * BD);
    float4* o1 = (float4*)(out + (size_t)B * DD + (size_t)b * BD);
    float4* o2 = (float4*)(out + (size_t)B * DD + (size_t)B * BD + (size_t)b * BD);

    #pragma unroll
    for (int it = 0; it < 16; ++it) {
        int i    = tid + 256 * it;
        int row  = i >> 5;
        int col4 = (i & 31) << 2;
        float4 a = A0g[i];
        float4 w = Wg[i];
        float4 x1, x2, m;
        x1.x = fmaf(t1, w.x, a.x); x1.y = fmaf(t1, w.y, a.y);
        x1.z = fmaf(t1, w.z, a.z); x1.w = fmaf(t1, w.w, a.w);
        x2.x = fmaf(t2, w.x, a.x); x2.y = fmaf(t2, w.y, a.y);
        x2.z = fmaf(t2, w.z, a.z); x2.w = fmaf(t2, w.w, a.w);
        o1[i] = x1;
        o2[i] = x2;
        m.x = h * fmaf(tm, w.x, a.x); m.y = h * fmaf(tm, w.y, a.y);
        m.z = h * fmaf(tm, w.z, a.z); m.w = h * fmaf(tm, w.w, a.w);
        *(float4*)(Om + row * 132 + col4) = m;
        // swizzled bf16 stores (8B each): chunk = col4/8, sub-half = (i&1)*8
        uint32_t off = (uint32_t)(row * 256 + ((((i & 31) >> 1) ^ (row & 7)) << 4) + ((i & 1) << 3));
        uint2 pa, pw;
        pa.x = b2u(__floats2bfloat162_rn(a.x, a.y)); pa.y = b2u(__floats2bfloat162_rn(a.z, a.w));
        pw.x = b2u(__floats2bfloat162_rn(w.x, w.y)); pw.y = b2u(__floats2bfloat162_rn(w.z, w.w));
        *(uint2*)(sm + AOP + off) = pa;
        *(uint2*)(sm + WOP + off) = pw;
    }
    __syncthreads();

    // ---- Phase 2: comm = A0@W + (-W)@A0 via HMMA; warp w owns rows 16w..16w+15 ----
    const uint32_t aA = sb + AOP;
    const uint32_t aW = sb + WOP;
    const int m0 = wid << 4;

    float acc[16][4];
    #pragma unroll
    for (int j = 0; j < 16; ++j)
        #pragma unroll
        for (int r = 0; r < 4; ++r) acc[j][r] = 0.0f;

    const int arow = (lane & 15);
    const int acol = (lane >> 4) << 3;

    #pragma unroll
    for (int k0 = 0; k0 < DD; k0 += 16) {
        uint32_t a1[4], a2[4];
        ldsm_x4(a1, taddr(aA, m0 + arow, k0 + acol));
        ldsm_x4(a2, taddr(aW, m0 + arow, k0 + acol));
        #pragma unroll
        for (int q = 0; q < 4; ++q) a2[q] ^= 0x80008000u;   // -W fragments
        #pragma unroll
        for (int j2 = 0; j2 < 8; ++j2) {
            int n0 = j2 << 4;
            uint32_t bW[4], bA[4];
            ldsm_x4t(bW, taddr(aW, k0 + arow, n0 + acol));
            ldsm_x4t(bA, taddr(aA, k0 + arow, n0 + acol));
            mma16816(acc[2 * j2],     a1, bW);
            mma16816(acc[2 * j2 + 1], a1, bW + 2);
            mma16816(acc[2 * j2],     a2, bA);
            mma16816(acc[2 * j2 + 1], a2, bA + 2);
        }
    }

    // ---- Phase 3: Omega = hM - c12*comm ----
    {
        const int lr = lane >> 2;
        const int lc = (lane & 3) << 1;
        #pragma unroll
        for (int jt = 0; jt < 16; ++jt) {
            int n0 = jt << 3;
            #pragma unroll
            for (int r = 0; r < 4; ++r) {
                int row = m0 + lr + ((r >> 1) << 3);
                int col = n0 + lc + (r & 1);
                float* p = Om + row * 132 + col;
                *p = fmaf(-c12, acc[jt][r], *p);
            }
        }
    }
    __syncthreads();

    // ---- Phase 4: y = expm(Omega) @ y0 via 14-term Taylor, Omega in registers ----
    const int r  = tid & 127;
    const int hh = tid >> 7;

    float om[64];
    {
        const float4* orr = (const float4*)(Om + (size_t)r * 132 + 64 * hh);
        #pragma unroll
        for (int q = 0; q < 16; ++q) {
            float4 f = orr[q];
            om[4 * q + 0] = f.x; om[4 * q + 1] = f.y;
            om[4 * q + 2] = f.z; om[4 * q + 3] = f.w;
        }
    }
    if (tid < DD) {
        float y0i = y0[(size_t)b * DD + tid];
        v[tid]  = y0i;
        yv[tid] = y0i;
    }
    __syncthreads();

    for (int k = 1; k <= 14; ++k) {
        const float4* vp = (const float4*)(v + 64 * hh);
        float s0 = 0.f, s1 = 0.f, s2 = 0.f, s3 = 0.f;
        #pragma unroll
        for (int q = 0; q < 16; ++q) {
            float4 f = vp[q];
            s0 = fmaf(om[4 * q + 0], f.x, s0);
            s1 = fmaf(om[4 * q + 1], f.y, s1);
            s2 = fmaf(om[4 * q + 2], f.z, s2);
            s3 = fmaf(om[4 * q + 3], f.w, s3);
        }
        ps[(hh << 7) + r] = (s0 + s1) + (s2 + s3);
        __syncthreads();
        if (tid < DD) {
            float nv = (ps[tid] + ps[DD + tid]) * (1.0f / (float)k);
            v[tid]   = nv;
            yv[tid] += nv;
        }
        __syncthreads();
    }

    if (tid < DD) out[(size_t)b * DD + tid] = yv[tid];
}

extern "C" void kernel_launch(void* const* d_in, const int* in_sizes, int n_in,
                              void* d_out, int out_size) {
    const float* t0 = (const float*)d_in[0];
    const float* h  = (const float*)d_in[1];
    const float* y0 = (const float*)d_in[2];
    const float* A0 = (const float*)d_in[3];
    const float* W  = (const float*)d_in[4];
    const int B = in_sizes[0];

    cudaFuncSetAttribute(magnus_kernel, cudaFuncAttributeMaxDynamicSharedMemorySize, SMEM_REQ);
    magnus_kernel<<<B, 256, SMEM_REQ>>>(t0, h, y0, A0, W, (float*)d_out, B);
}

// round 4
// speedup vs baseline: 4.2708x; 1.1323x over previous
#include <cuda_runtime.h>
#include <cuda_bf16.h>
#include <cstdint>

#define DD    128
#define BD    16384
#define SQ36  0.28867513459481287f

// ---- dynamic smem byte offsets ----
#define AOP    0           // bf16 A0 [128x128], pitch 256B, XOR swizzle (32KB)
#define WOP    32768       // bf16 W
#define OMEGA  65536       // fp32 128 x 132 (67584B)
#define VOFF   133120      // v[128]
#define PSOFF  133632      // ps[512]
#define SMEM_REQ 135680

__device__ __forceinline__ uint32_t smem_u32(const void* p) {
    uint32_t a;
    asm("{ .reg .u64 t; cvta.to.shared.u64 t, %1; cvt.u32.u64 %0, t; }" : "=r"(a) : "l"(p));
    return a;
}
__device__ __forceinline__ void ldsm_x4(uint32_t* r, uint32_t addr) {
    asm volatile("ldmatrix.sync.aligned.m8n8.x4.shared.b16 {%0,%1,%2,%3}, [%4];"
                 : "=r"(r[0]), "=r"(r[1]), "=r"(r[2]), "=r"(r[3]) : "r"(addr));
}
__device__ __forceinline__ void ldsm_x4t(uint32_t* r, uint32_t addr) {
    asm volatile("ldmatrix.sync.aligned.m8n8.x4.trans.shared.b16 {%0,%1,%2,%3}, [%4];"
                 : "=r"(r[0]), "=r"(r[1]), "=r"(r[2]), "=r"(r[3]) : "r"(addr));
}
__device__ __forceinline__ void mma16816(float* d, const uint32_t* a, const uint32_t* b) {
    asm volatile("mma.sync.aligned.m16n8k16.row.col.f32.bf16.bf16.f32 "
                 "{%0,%1,%2,%3}, {%4,%5,%6,%7}, {%8,%9}, {%0,%1,%2,%3};"
                 : "+f"(d[0]), "+f"(d[1]), "+f"(d[2]), "+f"(d[3])
                 : "r"(a[0]), "r"(a[1]), "r"(a[2]), "r"(a[3]), "r"(b[0]), "r"(b[1]));
}
__device__ __forceinline__ uint32_t taddr(uint32_t base, int row, int col) {
    int chunk = (col >> 3) ^ (row & 7);
    return base + row * 256 + (chunk << 4);
}
__device__ __forceinline__ uint32_t b2u(__nv_bfloat162 v) { return *reinterpret_cast<uint32_t*>(&v); }

__global__ __launch_bounds__(512, 1)
void magnus_kernel(const float* __restrict__ t0, const float* __restrict__ hp,
                   const float* __restrict__ y0,
                   const float* __restrict__ A0, const float* __restrict__ W,
                   float* __restrict__ out, int B)
{
    extern __shared__ char sm[];
    const uint32_t sb = smem_u32(sm);

    const int b    = blockIdx.x;
    const int tid  = threadIdx.x;
    const int lane = tid & 31;
    const int wid  = tid >> 5;

    const float h   = hp[0];
    const float t0b = t0[b];
    const float t1  = t0b + (0.5f - SQ36) * h;
    const float t2  = t0b + (0.5f + SQ36) * h;
    const float tm  = t0b + 0.5f * h;
    const float c12 = h * h * h * (1.0f / 12.0f);

    float* Om = (float*)(sm + OMEGA);   // 128 x 132 fp32
    float* v  = (float*)(sm + VOFF);
    float* ps = (float*)(sm + PSOFF);

    // ---- Phase 1: stream A0,W -> bf16 tiles + hM -> Omega; emit A1,A2 ----
    const float4* A0g = (const float4*)(A0 + (size_t)b * BD);
    const float4* Wg  = (const float4*)(W  + (size_t)b * BD);
    float4* o1 = (float4*)(out + (size_t)B * DD + (size_t)b * BD);
    float4* o2 = (float4*)(out + (size_t)B * DD + (size_t)B * BD + (size_t)b * BD);

    #pragma unroll
    for (int it = 0; it < 8; ++it) {
        int i    = tid + 512 * it;
        int row  = i >> 5;
        int col4 = (i & 31) << 2;
        float4 a = A0g[i];
        float4 w = Wg[i];
        float4 x1, x2, m;
        x1.x = fmaf(t1, w.x, a.x); x1.y = fmaf(t1, w.y, a.y);
        x1.z = fmaf(t1, w.z, a.z); x1.w = fmaf(t1, w.w, a.w);
        x2.x = fmaf(t2, w.x, a.x); x2.y = fmaf(t2, w.y, a.y);
        x2.z = fmaf(t2, w.z, a.z); x2.w = fmaf(t2, w.w, a.w);
        o1[i] = x1;
        o2[i] = x2;
        m.x = h * fmaf(tm, w.x, a.x); m.y = h * fmaf(tm, w.y, a.y);
        m.z = h * fmaf(tm, w.z, a.z); m.w = h * fmaf(tm, w.w, a.w);
        *(float4*)(Om + row * 132 + col4) = m;
        uint32_t off = (uint32_t)(row * 256 + ((((i & 31) >> 1) ^ (row & 7)) << 4) + ((i & 1) << 3));
        uint2 pa, pw;
        pa.x = b2u(__floats2bfloat162_rn(a.x, a.y)); pa.y = b2u(__floats2bfloat162_rn(a.z, a.w));
        pw.x = b2u(__floats2bfloat162_rn(w.x, w.y)); pw.y = b2u(__floats2bfloat162_rn(w.z, w.w));
        *(uint2*)(sm + AOP + off) = pa;
        *(uint2*)(sm + WOP + off) = pw;
    }
    __syncthreads();

    // ---- Phase 2: comm = A0@W + (-W)@A0, 4x4 warp grid, 32x32 tile/warp ----
    const uint32_t aA = sb + AOP;
    const uint32_t aW = sb + WOP;
    const int m0 = (wid >> 2) << 5;
    const int n0 = (wid & 3) << 5;
    const int arow = lane & 15;
    const int acol = (lane >> 4) << 3;

    float acc[2][4][4];
    #pragma unroll
    for (int mh = 0; mh < 2; ++mh)
        #pragma unroll
        for (int nt = 0; nt < 4; ++nt)
            #pragma unroll
            for (int r = 0; r < 4; ++r) acc[mh][nt][r] = 0.0f;

    #pragma unroll
    for (int k0 = 0; k0 < DD; k0 += 16) {
        uint32_t aA1[4], aA2[4], aW1[4], aW2[4];
        ldsm_x4(aA1, taddr(aA, m0 + arow,      k0 + acol));
        ldsm_x4(aA2, taddr(aA, m0 + 16 + arow, k0 + acol));
        ldsm_x4(aW1, taddr(aW, m0 + arow,      k0 + acol));
        ldsm_x4(aW2, taddr(aW, m0 + 16 + arow, k0 + acol));
        #pragma unroll
        for (int q = 0; q < 4; ++q) { aW1[q] ^= 0x80008000u; aW2[q] ^= 0x80008000u; }
        #pragma unroll
        for (int nn = 0; nn < 2; ++nn) {
            uint32_t bW[4], bA[4];
            ldsm_x4t(bW, taddr(aW, k0 + arow, n0 + nn * 16 + acol));
            ldsm_x4t(bA, taddr(aA, k0 + arow, n0 + nn * 16 + acol));
            mma16816(acc[0][2 * nn],     aA1, bW);
            mma16816(acc[0][2 * nn + 1], aA1, bW + 2);
            mma16816(acc[1][2 * nn],     aA2, bW);
            mma16816(acc[1][2 * nn + 1], aA2, bW + 2);
            mma16816(acc[0][2 * nn],     aW1, bA);
            mma16816(acc[0][2 * nn + 1], aW1, bA + 2);
            mma16816(acc[1][2 * nn],     aW2, bA);
            mma16816(acc[1][2 * nn + 1], aW2, bA + 2);
        }
    }

    // ---- Phase 3: Omega = hM - c12*comm ----
    {
        const int lr = lane >> 2;
        const int lc = (lane & 3) << 1;
        #pragma unroll
        for (int mh = 0; mh < 2; ++mh)
            #pragma unroll
            for (int nt = 0; nt < 4; ++nt)
                #pragma unroll
                for (int r = 0; r < 4; ++r) {
                    int row = m0 + mh * 16 + lr + ((r >> 1) << 3);
                    int col = n0 + nt * 8 + lc + (r & 1);
                    float* p = Om + row * 132 + col;
                    *p = fmaf(-c12, acc[mh][nt][r], *p);
                }
    }
    __syncthreads();

    // ---- Phase 4: y = expm(Omega) @ y0 (10-term Taylor), 32-col quarter/thread ----
    const int r  = tid & 127;
    const int q  = tid >> 7;              // 0..3

    float om[32];
    {
        const float4* orr = (const float4*)(Om + (size_t)r * 132 + 32 * q);
        #pragma unroll
        for (int j = 0; j < 8; ++j) {
            float4 f = orr[j];
            om[4 * j + 0] = f.x; om[4 * j + 1] = f.y;
            om[4 * j + 2] = f.z; om[4 * j + 3] = f.w;
        }
    }
    float yvreg = 0.0f;
    if (q == 0) {
        float y0i = y0[(size_t)b * DD + r];
        v[r]  = y0i;
        yvreg = y0i;
    }
    __syncthreads();

    #pragma unroll 1
    for (int k = 1; k <= 10; ++k) {
        const float4* vp = (const float4*)(v + 32 * q);
        float s0 = 0.f, s1 = 0.f, s2 = 0.f, s3 = 0.f;
        #pragma unroll
        for (int j = 0; j < 8; ++j) {
            float4 f = vp[j];
            s0 = fmaf(om[4 * j + 0], f.x, s0);
            s1 = fmaf(om[4 * j + 1], f.y, s1);
            s2 = fmaf(om[4 * j + 2], f.z, s2);
            s3 = fmaf(om[4 * j + 3], f.w, s3);
        }
        ps[(q << 7) + r] = (s0 + s1) + (s2 + s3);
        __syncthreads();
        if (q == 0) {
            float nv = (ps[r] + ps[128 + r] + ps[256 + r] + ps[384 + r]) * (1.0f / (float)k);
            v[r]   = nv;
            yvreg += nv;
        }
        __syncthreads();
    }

    if (q == 0) out[(size_t)b * DD + r] = yvreg;
}

extern "C" void kernel_launch(void* const* d_in, const int* in_sizes, int n_in,
                              void* d_out, int out_size) {
    const float* t0 = (const float*)d_in[0];
    const float* h  = (const float*)d_in[1];
    const float* y0 = (const float*)d_in[2];
    const float* A0 = (const float*)d_in[3];
    const float* W  = (const float*)d_in[4];
    const int B = in_sizes[0];

    cudaFuncSetAttribute(magnus_kernel, cudaFuncAttributeMaxDynamicSharedMemorySize, SMEM_REQ);
    magnus_kernel<<<B, 512, SMEM_REQ>>>(t0, h, y0, A0, W, (float*)d_out, B);
}